// round 6
// baseline (speedup 1.0000x reference)
#include <cuda_runtime.h>
#include <cuda_fp16.h>
#include <cstdint>
#include <cstddef>

// Fixed problem sizes
#define NN 100000
#define NR 8
#define DD 128
#define EE 800000
#define NW 9                       // 8 relations + root
#define SEG (NN * NR)              // 800000 segments (dst,rel)
#define NTILES 782                 // ceil(NN/128)
#define NBLK2 3125                 // ceil(SEG/256)
#define XSH 136                    // smem row stride in halfs

#define ABH 17408                  // 128*XSH halfs per buffer
#define OFF_RP   139264            // byte offset of rowptr cache (4*ABH*2)
#define OFF_INV  143364            // + 1025*4
#define OFF_BIAS 147460            // + 4096
#define SMEMB    147972            // + 512

// ---------------------------------------------------------------------------
// Device scratch
// ---------------------------------------------------------------------------
__device__ __half g_xh[(size_t)NN * DD];      // 25.6 MB emb fp16
__device__ __half g_x1h[(size_t)NN * DD];     // 25.6 MB relu(layer1) fp16
__device__ __half g_Wh[2 * NW * DD * DD];     // both layers W[w][k][o] fp16
__device__ int    g_cnt[SEG];
__device__ float  g_inv[SEG];
__device__ int    g_rowptr[SEG + 1];
__device__ int    g_dpos[SEG];
__device__ int    g_bsum[NBLK2];
__device__ int    g_esrc[EE];                 // src node, sorted by (dst,rel)

// ---------------------------------------------------------------------------
// PTX helpers
// ---------------------------------------------------------------------------
__device__ __forceinline__ uint32_t sptr(const void* p) {
    return (uint32_t)__cvta_generic_to_shared(p);
}
__device__ __forceinline__ void ldsm4(uint32_t* r, uint32_t addr) {
    asm volatile("ldmatrix.sync.aligned.m8n8.x4.shared.b16 {%0,%1,%2,%3}, [%4];"
                 : "=r"(r[0]), "=r"(r[1]), "=r"(r[2]), "=r"(r[3]) : "r"(addr));
}
__device__ __forceinline__ void ldsm4t(uint32_t* r, uint32_t addr) {
    asm volatile("ldmatrix.sync.aligned.m8n8.x4.trans.shared.b16 {%0,%1,%2,%3}, [%4];"
                 : "=r"(r[0]), "=r"(r[1]), "=r"(r[2]), "=r"(r[3]) : "r"(addr));
}
__device__ __forceinline__ void mma_f16(float* d, const uint32_t* a, uint32_t b0, uint32_t b1) {
    asm volatile(
        "mma.sync.aligned.m16n8k16.row.col.f32.f16.f16.f32 "
        "{%0,%1,%2,%3}, {%4,%5,%6,%7}, {%8,%9}, {%0,%1,%2,%3};"
        : "+f"(d[0]), "+f"(d[1]), "+f"(d[2]), "+f"(d[3])
        : "r"(a[0]), "r"(a[1]), "r"(a[2]), "r"(a[3]), "r"(b0), "r"(b1));
}
__device__ __forceinline__ void cp_async16(uint32_t smem_addr, const void* gptr) {
    asm volatile("cp.async.cg.shared.global [%0], [%1], 16;" :: "r"(smem_addr), "l"(gptr));
}
#define CP_COMMIT() asm volatile("cp.async.commit_group;" ::: "memory")
#define CP_WAIT0()  asm volatile("cp.async.wait_group 0;" ::: "memory")

__device__ __forceinline__ void addrow(float* af, uint4 q0, uint4 q1) {
    const __half2* h0 = (const __half2*)&q0;
    const __half2* h1 = (const __half2*)&q1;
#pragma unroll
    for (int j = 0; j < 4; j++) {
        float2 f = __half22float2(h0[j]);
        af[2 * j] += f.x; af[2 * j + 1] += f.y;
        float2 g = __half22float2(h1[j]);
        af[8 + 2 * j] += g.x; af[8 + 2 * j + 1] += g.y;
    }
}

// ---------------------------------------------------------------------------
// Preprocessing
// ---------------------------------------------------------------------------
__global__ void init_kernel(const float* __restrict__ emb) {
    int i = blockIdx.x * blockDim.x + threadIdx.x;       // 3.2M threads
    if (i < SEG) g_cnt[i] = 0;
    if (i < NN * DD / 4) {
        float4 v = *((const float4*)emb + i);
        __half2* p = (__half2*)(g_xh + (size_t)i * 4);
        p[0] = __floats2half2_rn(v.x, v.y);
        p[1] = __floats2half2_rn(v.z, v.w);
    }
}

__global__ void count_kernel(const int* __restrict__ ei, const int* __restrict__ et) {
    int e = blockIdx.x * blockDim.x + threadIdx.x;
    if (e < EE) atomicAdd(&g_cnt[ei[EE + e] * NR + et[e]], 1);
}

__global__ void scan1_kernel() {
    __shared__ int sc[256];
    int i = blockIdx.x * 256 + threadIdx.x;
    sc[threadIdx.x] = (i < SEG) ? g_cnt[i] : 0;
    __syncthreads();
    for (int off = 128; off > 0; off >>= 1) {
        if (threadIdx.x < off) sc[threadIdx.x] += sc[threadIdx.x + off];
        __syncthreads();
    }
    if (threadIdx.x == 0) g_bsum[blockIdx.x] = sc[0];
}

__global__ void scan2_kernel() {     // shuffle-based exclusive scan of g_bsum
    __shared__ int wsum[32];
    __shared__ int carry_s;
    int tid = threadIdx.x;
    if (tid == 0) carry_s = 0;
    __syncthreads();
    for (int base = 0; base < NBLK2; base += 1024) {
        int c = carry_s;
        int i = base + tid;
        int v = (i < NBLK2) ? g_bsum[i] : 0;
        int x = v;
#pragma unroll
        for (int off = 1; off < 32; off <<= 1) {
            int t = __shfl_up_sync(0xffffffffu, x, off);
            if ((tid & 31) >= off) x += t;
        }
        if ((tid & 31) == 31) wsum[tid >> 5] = x;
        __syncthreads();
        if (tid < 32) {
            int y = wsum[tid];
#pragma unroll
            for (int off = 1; off < 32; off <<= 1) {
                int t = __shfl_up_sync(0xffffffffu, y, off);
                if (tid >= off) y += t;
            }
            wsum[tid] = y;
        }
        __syncthreads();
        int incl = x + ((tid >= 32) ? wsum[(tid >> 5) - 1] : 0);
        int tot = wsum[31];
        if (i < NBLK2) g_bsum[i] = c + incl - v;
        __syncthreads();
        if (tid == 0) carry_s = c + tot;
        __syncthreads();
    }
    if (tid == 0) g_rowptr[SEG] = EE;
}

__global__ void scan3_kernel() {     // rowptr + dpos + inv
    __shared__ int sc[256];
    int i = blockIdx.x * 256 + threadIdx.x;
    int c = (i < SEG) ? g_cnt[i] : 0;
    sc[threadIdx.x] = c;
    __syncthreads();
    for (int off = 1; off < 256; off <<= 1) {
        int v = (threadIdx.x >= off) ? sc[threadIdx.x - off] : 0;
        __syncthreads();
        sc[threadIdx.x] += v;
        __syncthreads();
    }
    if (i < SEG) {
        int rp = g_bsum[blockIdx.x] + sc[threadIdx.x] - c;
        g_rowptr[i] = rp;
        g_dpos[i] = rp;
        g_inv[i] = 1.0f / fmaxf((float)c, 1.0f);
    }
}

__global__ void fill_kernel(const int* __restrict__ ei, const int* __restrict__ et) {
    int e = blockIdx.x * blockDim.x + threadIdx.x;
    if (e >= EE) return;
    int seg = ei[EE + e] * NR + et[e];
    int pos = atomicAdd(&g_dpos[seg], 1);
    g_esrc[pos] = ei[e];
}

// both layers' weights: g_Wh[layer][w][k][o] fp16 (k-major)
__global__ void prep_wh_kernel(const float* __restrict__ c1, const float* __restrict__ b1,
                               const float* __restrict__ r1, const float* __restrict__ c2,
                               const float* __restrict__ b2, const float* __restrict__ r2) {
    int idx = blockIdx.x * blockDim.x + threadIdx.x;     // 2*NW*DD*DD
    if (idx >= 2 * NW * DD * DD) return;
    int layer = idx >= NW * DD * DD;
    int id = idx - layer * NW * DD * DD;
    const float* comp = layer ? c2 : c1;
    const float* basis = layer ? b2 : b1;
    const float* root = layer ? r2 : r1;
    int w = id >> 14;
    int rem = id & 16383;
    int k = rem >> 7, o = rem & 127;
    float v;
    if (w < NR) {
        v = 0.f;
#pragma unroll
        for (int b = 0; b < 8; b++)
            v += comp[w * 8 + b] * basis[((size_t)b * DD + k) * DD + o];
    } else {
        v = root[k * DD + o];
    }
    g_Wh[idx] = __float2half_rn(v);
}

// ---------------------------------------------------------------------------
// MMA K-half over A[128,K] x W[K,128] fragment loop
// ---------------------------------------------------------------------------
__device__ __forceinline__ void mma_half(float (&acc)[2][8][4], const __half* As,
                                         const __half* Wc, int kbeg, int kend,
                                         int m0, int n0, int arow, int acol8) {
#pragma unroll
    for (int k0 = kbeg; k0 < kend; k0 += 16) {
        uint32_t a[2][4];
#pragma unroll
        for (int mi = 0; mi < 2; mi++)
            ldsm4(a[mi], sptr(As + (m0 + mi * 16 + arow) * XSH + k0 + acol8));
        uint32_t bb[4][4];
#pragma unroll
        for (int np = 0; np < 4; np++)
            ldsm4t(bb[np], sptr(Wc + (k0 + arow) * XSH + n0 + np * 16 + acol8));
#pragma unroll
        for (int mi = 0; mi < 2; mi++)
#pragma unroll
            for (int ni = 0; ni < 8; ni++)
                mma_f16(acc[mi][ni], a[mi],
                        bb[ni >> 1][(ni & 1) * 2], bb[ni >> 1][(ni & 1) * 2 + 1]);
    }
}

// ---------------------------------------------------------------------------
// Fused kernel with gather/MMA software pipeline (double-buffered A and W)
// ---------------------------------------------------------------------------
__global__ void __launch_bounds__(256, 1)
fused_kernel(const __half* __restrict__ Xsrc, const __half* __restrict__ Wbase,
             const float* __restrict__ bias, float* __restrict__ out32,
             __half* __restrict__ outh) {
    extern __shared__ char smraw[];
    __half* SA = (__half*)smraw;                 // 2 x ABH
    __half* SW = (__half*)smraw + 2 * ABH;       // 2 x ABH
    int*   srp  = (int*)(smraw + OFF_RP);        // 1025
    float* sinv = (float*)(smraw + OFF_INV);     // 1024
    float* sbias = (float*)(smraw + OFF_BIAS);   // 128

    const int tid = threadIdx.x, wid = tid >> 5, lane = tid & 31;
    const int row0 = blockIdx.x * 128;
    const int seg0 = row0 * NR;
    const int sub = lane >> 3, sl = lane & 7;
    const uint4 Z4 = make_uint4(0u, 0u, 0u, 0u);

    for (int i = tid; i < 1025; i += 256) {
        int s = seg0 + i;
        srp[i] = (s <= SEG) ? g_rowptr[s] : EE;
    }
    for (int i = tid; i < 1024; i += 256) {
        int s = seg0 + i;
        sinv[i] = (s < SEG) ? g_inv[s] : 0.f;
    }
    if (tid < 128) sbias[tid] = bias[tid];

    // prefetch W[0]
    for (int c = tid; c < 2048; c += 256) {
        int k = c >> 4, c8 = c & 15;
        cp_async16(sptr(SW + k * XSH + c8 * 8), Wbase + k * DD + c8 * 8);
    }
    __syncthreads();   // srp/sinv visible

    // ---- preamble: stage A[0] (relation 0) ----
    {
#pragma unroll
        for (int j = 0; j < 4; j++) {
            int row = wid * 16 + j * 4 + sub;
            int idx = row * NR;
            int rp = srp[idx], dg = srp[idx + 1] - rp;
            __half* dst = SA + row * XSH + sl * 16;
            if (dg == 1) {
                int s0 = g_esrc[rp];
                cp_async16(sptr(dst), Xsrc + (size_t)s0 * DD + sl * 16);
                cp_async16(sptr(dst) + 16, Xsrc + (size_t)s0 * DD + sl * 16 + 8);
            } else if (dg == 0) {
                *(uint4*)dst = Z4;
                *(uint4*)(dst + 8) = Z4;
            } else {
                float af[16];
#pragma unroll
                for (int q = 0; q < 16; q++) af[q] = 0.f;
                for (int e = rp; e < rp + dg; e++) {
                    int src = g_esrc[e];
                    const uint4* p = (const uint4*)(Xsrc + (size_t)src * DD) + sl * 2;
                    addrow(af, p[0], p[1]);
                }
                float s = sinv[idx];
                uint4 o0, o1;
                __half2* h0 = (__half2*)&o0;
                __half2* h1 = (__half2*)&o1;
#pragma unroll
                for (int q = 0; q < 4; q++) {
                    h0[q] = __floats2half2_rn(af[2 * q] * s, af[2 * q + 1] * s);
                    h1[q] = __floats2half2_rn(af[8 + 2 * q] * s, af[8 + 2 * q + 1] * s);
                }
                *(uint4*)dst = o0;
                *(uint4*)(dst + 8) = o1;
            }
        }
    }
    CP_COMMIT();   // W[0] + deg-1 gathers of relation 0

    float acc[2][8][4];
#pragma unroll
    for (int mi = 0; mi < 2; mi++)
#pragma unroll
        for (int ni = 0; ni < 8; ni++)
#pragma unroll
            for (int j = 0; j < 4; j++) acc[mi][ni][j] = 0.f;

    const int m0 = (wid >> 1) * 32, n0 = (wid & 1) * 64;
    const int arow = lane & 15, acol8 = (lane >> 4) * 8;

    for (int w = 0; w < NW; w++) {
        __half* Acur = SA + (w & 1) * ABH;
        __half* Anxt = SA + ((w + 1) & 1) * ABH;
        const int rel = w + 1;

        // (1) esrc prefetch for next relation
        int rp[4], dg[4], s0[4], s1[4];
        if (rel < NR) {
#pragma unroll
            for (int j = 0; j < 4; j++) {
                int row = wid * 16 + j * 4 + sub;
                int idx = row * NR + rel;
                rp[j] = srp[idx];
                dg[j] = srp[idx + 1] - rp[j];
                s0[j] = (dg[j] >= 1) ? g_esrc[rp[j]] : 0;
                s1[j] = (dg[j] >= 2) ? g_esrc[rp[j] + 1] : 0;
            }
        }

        // (3) all prior cp.async groups done (W[w], prior gathers)
        CP_WAIT0();
        __syncthreads();

        // (4.5) prefetch W[w+1]; root A-tile staged via cp.async at w==7
        if (w + 1 < NW) {
            const __half* srcW = Wbase + (size_t)(w + 1) * DD * DD;
            __half* wd = SW + ((w + 1) & 1) * ABH;
            for (int c = tid; c < 2048; c += 256) {
                int k = c >> 4, c8 = c & 15;
                cp_async16(sptr(wd + k * XSH + c8 * 8), srcW + k * DD + c8 * 8);
            }
            if (w + 1 == NR) {
                for (int c = tid; c < 2048; c += 256) {
                    int r = c >> 4, c8 = c & 15;
                    int g = row0 + r;
                    if (g < NN)
                        cp_async16(sptr(Anxt + r * XSH + c8 * 8),
                                   Xsrc + (size_t)g * DD + c8 * 8);
                    else
                        *(uint4*)(Anxt + r * XSH + c8 * 8) = Z4;
                }
            }
            CP_COMMIT();
        }

        __half* Wc = SW + (w & 1) * ABH;

        // (5) MMA half 1 covers esrc latency
        mma_half(acc, Acur, Wc, 0, 64, m0, n0, arow, acol8);

        // (6) x-row loads / cp.async / zeros for next relation
        uint4 x0a[4], x0b[4];
        if (rel < NR) {
#pragma unroll
            for (int j = 0; j < 4; j++) {
                int row = wid * 16 + j * 4 + sub;
                __half* dst = Anxt + row * XSH + sl * 16;
                if (dg[j] == 1) {
                    cp_async16(sptr(dst), Xsrc + (size_t)s0[j] * DD + sl * 16);
                    cp_async16(sptr(dst) + 16, Xsrc + (size_t)s0[j] * DD + sl * 16 + 8);
                } else if (dg[j] >= 2) {
                    const uint4* p = (const uint4*)(Xsrc + (size_t)s0[j] * DD) + sl * 2;
                    x0a[j] = p[0];
                    x0b[j] = p[1];
                } else {
                    *(uint4*)dst = Z4;
                    *(uint4*)(dst + 8) = Z4;
                }
            }
        }

        // (7) MMA half 2 covers x latency
        mma_half(acc, Acur, Wc, 64, 128, m0, n0, arow, acol8);

        // (8) finalize deg>=2 rows
        if (rel < NR) {
#pragma unroll
            for (int j = 0; j < 4; j++) {
                if (dg[j] >= 2) {
                    int row = wid * 16 + j * 4 + sub;
                    int idx = row * NR + rel;
                    float af[16];
#pragma unroll
                    for (int q = 0; q < 16; q++) af[q] = 0.f;
                    addrow(af, x0a[j], x0b[j]);
                    const uint4* p1 = (const uint4*)(Xsrc + (size_t)s1[j] * DD) + sl * 2;
                    addrow(af, p1[0], p1[1]);
                    for (int e = rp[j] + 2; e < rp[j] + dg[j]; e++) {
                        int src = g_esrc[e];
                        const uint4* q = (const uint4*)(Xsrc + (size_t)src * DD) + sl * 2;
                        addrow(af, q[0], q[1]);
                    }
                    float s = sinv[idx];
                    uint4 o0, o1;
                    __half2* h0 = (__half2*)&o0;
                    __half2* h1 = (__half2*)&o1;
#pragma unroll
                    for (int q = 0; q < 4; q++) {
                        h0[q] = __floats2half2_rn(af[2 * q] * s, af[2 * q + 1] * s);
                        h1[q] = __floats2half2_rn(af[8 + 2 * q] * s, af[8 + 2 * q + 1] * s);
                    }
                    __half* dst = Anxt + row * XSH + sl * 16;
                    *(uint4*)dst = o0;
                    *(uint4*)(dst + 8) = o1;
                }
            }
            // (9) commit gather cp.asyncs of this relation
            CP_COMMIT();
        }
    }

    // ---- epilogue ----
#pragma unroll
    for (int mi = 0; mi < 2; mi++) {
#pragma unroll
        for (int part = 0; part < 2; part++) {
            int row = m0 + mi * 16 + (lane >> 2) + part * 8;
            int g = row0 + row;
            if (g < NN) {
                if (out32) {
                    float* base = out32 + (size_t)g * DD;
#pragma unroll
                    for (int ni = 0; ni < 8; ni++) {
                        int col = n0 + ni * 8 + 2 * (lane & 3);
                        float2 v;
                        v.x = acc[mi][ni][part * 2] + sbias[col];
                        v.y = acc[mi][ni][part * 2 + 1] + sbias[col + 1];
                        *(float2*)(base + col) = v;
                    }
                } else {
                    __half* base = outh + (size_t)g * DD;
#pragma unroll
                    for (int ni = 0; ni < 8; ni++) {
                        int col = n0 + ni * 8 + 2 * (lane & 3);
                        float vx = fmaxf(acc[mi][ni][part * 2] + sbias[col], 0.f);
                        float vy = fmaxf(acc[mi][ni][part * 2 + 1] + sbias[col + 1], 0.f);
                        *(__half2*)(base + col) = __floats2half2_rn(vx, vy);
                    }
                }
            }
        }
    }
}

// ---------------------------------------------------------------------------
extern "C" void kernel_launch(void* const* d_in, const int* in_sizes, int n_in,
                              void* d_out, int out_size) {
    const int*   ei     = (const int*)d_in[0];
    const int*   et     = (const int*)d_in[1];
    const float* emb    = (const float*)d_in[2];
    const float* basis1 = (const float*)d_in[3];
    const float* comp1  = (const float*)d_in[4];
    const float* root1  = (const float*)d_in[5];
    const float* bias1  = (const float*)d_in[6];
    const float* basis2 = (const float*)d_in[7];
    const float* comp2  = (const float*)d_in[8];
    const float* root2  = (const float*)d_in[9];
    const float* bias2  = (const float*)d_in[10];
    float* out = (float*)d_out;

    cudaFuncSetAttribute(fused_kernel, cudaFuncAttributeMaxDynamicSharedMemorySize,
                         SMEMB);

    __half *xh, *x1h, *wh;
    cudaGetSymbolAddress((void**)&xh, g_xh);
    cudaGetSymbolAddress((void**)&x1h, g_x1h);
    cudaGetSymbolAddress((void**)&wh, g_Wh);

    init_kernel<<<12500, 256>>>(emb);
    count_kernel<<<NBLK2, 256>>>(ei, et);
    scan1_kernel<<<NBLK2, 256>>>();
    scan2_kernel<<<1, 1024>>>();
    scan3_kernel<<<NBLK2, 256>>>();
    fill_kernel<<<NBLK2, 256>>>(ei, et);
    prep_wh_kernel<<<1152, 256>>>(comp1, basis1, root1, comp2, basis2, root2);

    // layer 1: g_xh -> relu -> g_x1h (fp16)
    fused_kernel<<<NTILES, 256, SMEMB>>>(xh, wh, bias1, nullptr, x1h);
    // layer 2: g_x1h -> out (fp32 + bias)
    fused_kernel<<<NTILES, 256, SMEMB>>>(x1h, wh + NW * DD * DD, bias2, out, nullptr);
}

// round 7
// speedup vs baseline: 1.4380x; 1.4380x over previous
#include <cuda_runtime.h>
#include <cuda_fp16.h>
#include <cstdint>
#include <cstddef>

// Fixed problem sizes
#define NN 100000
#define NR 8
#define DD 128
#define EE 800000
#define NW 9                       // 8 relations + root
#define SEG (NN * NR)              // 800000 segments (dst,rel)
#define NTILES 782                 // ceil(NN/128)
#define NBLK2 3125                 // ceil(SEG/256)
#define XSH 136                    // smem row stride in halfs

#define ABH (128 * XSH)            // 17408 halfs per tile buffer
// smem layout (bytes): As | W0 | W1 | bias | srp
#define OFF_BIAS (3 * ABH * 2)             // 104448
#define OFF_RP   (OFF_BIAS + 512)          // 104960
#define SMEMB    (OFF_RP + 1032 * 4)       // 109088 -> 2 CTAs/SM

// ---------------------------------------------------------------------------
// Device scratch
// ---------------------------------------------------------------------------
__device__ __half g_xh[(size_t)NN * DD];      // 25.6 MB emb fp16
__device__ __half g_x1h[(size_t)NN * DD];     // 25.6 MB relu(layer1) fp16
__device__ __half g_Wh[2 * NW * DD * DD];     // both layers W[w][k][o] fp16
__device__ int    g_cnt[SEG];
__device__ int    g_rowptr[SEG + 1];
__device__ int    g_dpos[SEG];
__device__ int    g_bsum[NBLK2];
__device__ int    g_esrc[EE];                 // src node, sorted by (dst,rel)

// ---------------------------------------------------------------------------
// PTX helpers
// ---------------------------------------------------------------------------
__device__ __forceinline__ uint32_t sptr(const void* p) {
    return (uint32_t)__cvta_generic_to_shared(p);
}
__device__ __forceinline__ void ldsm4(uint32_t* r, uint32_t addr) {
    asm volatile("ldmatrix.sync.aligned.m8n8.x4.shared.b16 {%0,%1,%2,%3}, [%4];"
                 : "=r"(r[0]), "=r"(r[1]), "=r"(r[2]), "=r"(r[3]) : "r"(addr));
}
__device__ __forceinline__ void ldsm4t(uint32_t* r, uint32_t addr) {
    asm volatile("ldmatrix.sync.aligned.m8n8.x4.trans.shared.b16 {%0,%1,%2,%3}, [%4];"
                 : "=r"(r[0]), "=r"(r[1]), "=r"(r[2]), "=r"(r[3]) : "r"(addr));
}
__device__ __forceinline__ void mma_f16(float* d, const uint32_t* a, uint32_t b0, uint32_t b1) {
    asm volatile(
        "mma.sync.aligned.m16n8k16.row.col.f32.f16.f16.f32 "
        "{%0,%1,%2,%3}, {%4,%5,%6,%7}, {%8,%9}, {%0,%1,%2,%3};"
        : "+f"(d[0]), "+f"(d[1]), "+f"(d[2]), "+f"(d[3])
        : "r"(a[0]), "r"(a[1]), "r"(a[2]), "r"(a[3]), "r"(b0), "r"(b1));
}
__device__ __forceinline__ void cp_async16(uint32_t smem_addr, const void* gptr) {
    asm volatile("cp.async.cg.shared.global [%0], [%1], 16;" :: "r"(smem_addr), "l"(gptr));
}
#define CP_COMMIT() asm volatile("cp.async.commit_group;" ::: "memory")
#define CP_WAIT(n)  asm volatile("cp.async.wait_group %0;" :: "n"(n) : "memory")

__device__ __forceinline__ void addrow(float* af, uint4 q0, uint4 q1) {
    const __half2* h0 = (const __half2*)&q0;
    const __half2* h1 = (const __half2*)&q1;
#pragma unroll
    for (int j = 0; j < 4; j++) {
        float2 f = __half22float2(h0[j]);
        af[2 * j] += f.x; af[2 * j + 1] += f.y;
        float2 g = __half22float2(h1[j]);
        af[8 + 2 * j] += g.x; af[8 + 2 * j + 1] += g.y;
    }
}

// ---------------------------------------------------------------------------
// Preprocessing
// ---------------------------------------------------------------------------
__global__ void init_kernel(const float* __restrict__ emb) {
    int i = blockIdx.x * blockDim.x + threadIdx.x;       // 3.2M threads
    if (i < SEG) g_cnt[i] = 0;
    if (i < NN * DD / 4) {
        float4 v = *((const float4*)emb + i);
        __half2* p = (__half2*)(g_xh + (size_t)i * 4);
        p[0] = __floats2half2_rn(v.x, v.y);
        p[1] = __floats2half2_rn(v.z, v.w);
    }
}

__global__ void count_kernel(const int* __restrict__ ei, const int* __restrict__ et) {
    int e = blockIdx.x * blockDim.x + threadIdx.x;
    if (e < EE) atomicAdd(&g_cnt[ei[EE + e] * NR + et[e]], 1);
}

__global__ void scan1_kernel() {
    __shared__ int sc[256];
    int i = blockIdx.x * 256 + threadIdx.x;
    sc[threadIdx.x] = (i < SEG) ? g_cnt[i] : 0;
    __syncthreads();
    for (int off = 128; off > 0; off >>= 1) {
        if (threadIdx.x < off) sc[threadIdx.x] += sc[threadIdx.x + off];
        __syncthreads();
    }
    if (threadIdx.x == 0) g_bsum[blockIdx.x] = sc[0];
}

__global__ void scan2_kernel() {     // shuffle-based exclusive scan of g_bsum
    __shared__ int wsum[32];
    __shared__ int carry_s;
    int tid = threadIdx.x;
    if (tid == 0) carry_s = 0;
    __syncthreads();
    for (int base = 0; base < NBLK2; base += 1024) {
        int c = carry_s;
        int i = base + tid;
        int v = (i < NBLK2) ? g_bsum[i] : 0;
        int x = v;
#pragma unroll
        for (int off = 1; off < 32; off <<= 1) {
            int t = __shfl_up_sync(0xffffffffu, x, off);
            if ((tid & 31) >= off) x += t;
        }
        if ((tid & 31) == 31) wsum[tid >> 5] = x;
        __syncthreads();
        if (tid < 32) {
            int y = wsum[tid];
#pragma unroll
            for (int off = 1; off < 32; off <<= 1) {
                int t = __shfl_up_sync(0xffffffffu, y, off);
                if (tid >= off) y += t;
            }
            wsum[tid] = y;
        }
        __syncthreads();
        int incl = x + ((tid >= 32) ? wsum[(tid >> 5) - 1] : 0);
        int tot = wsum[31];
        if (i < NBLK2) g_bsum[i] = c + incl - v;
        __syncthreads();
        if (tid == 0) carry_s = c + tot;
        __syncthreads();
    }
    if (tid == 0) g_rowptr[SEG] = EE;
}

__global__ void scan3_kernel() {     // rowptr + fill cursors
    __shared__ int sc[256];
    int i = blockIdx.x * 256 + threadIdx.x;
    int c = (i < SEG) ? g_cnt[i] : 0;
    sc[threadIdx.x] = c;
    __syncthreads();
    for (int off = 1; off < 256; off <<= 1) {
        int v = (threadIdx.x >= off) ? sc[threadIdx.x - off] : 0;
        __syncthreads();
        sc[threadIdx.x] += v;
        __syncthreads();
    }
    if (i < SEG) {
        int rp = g_bsum[blockIdx.x] + sc[threadIdx.x] - c;
        g_rowptr[i] = rp;
        g_dpos[i] = rp;
    }
}

__global__ void fill_kernel(const int* __restrict__ ei, const int* __restrict__ et) {
    int e = blockIdx.x * blockDim.x + threadIdx.x;
    if (e >= EE) return;
    int seg = ei[EE + e] * NR + et[e];
    int pos = atomicAdd(&g_dpos[seg], 1);
    g_esrc[pos] = ei[e];
}

// both layers' weights: g_Wh[layer][w][k][o] fp16 (k-major)
__global__ void prep_wh_kernel(const float* __restrict__ c1, const float* __restrict__ b1,
                               const float* __restrict__ r1, const float* __restrict__ c2,
                               const float* __restrict__ b2, const float* __restrict__ r2) {
    int idx = blockIdx.x * blockDim.x + threadIdx.x;     // 2*NW*DD*DD
    if (idx >= 2 * NW * DD * DD) return;
    int layer = idx >= NW * DD * DD;
    int id = idx - layer * NW * DD * DD;
    const float* comp = layer ? c2 : c1;
    const float* basis = layer ? b2 : b1;
    const float* root = layer ? r2 : r1;
    int w = id >> 14;
    int rem = id & 16383;
    int k = rem >> 7, o = rem & 127;
    float v;
    if (w < NR) {
        v = 0.f;
#pragma unroll
        for (int b = 0; b < 8; b++)
            v += comp[w * 8 + b] * basis[((size_t)b * DD + k) * DD + o];
    } else {
        v = root[k * DD + o];
    }
    g_Wh[idx] = __float2half_rn(v);
}

// ---------------------------------------------------------------------------
// Fused kernel (R5 structure, 2 CTAs/SM): per 128-dst tile, for each relation
// build mean-agg A-tile in smem (quarter-warp gather, deg1 via cp.async),
// MMA against double-buffered W; root block staged by cp.async.
// ---------------------------------------------------------------------------
__global__ void __launch_bounds__(256, 2)
fused_kernel(const __half* __restrict__ Xsrc, const __half* __restrict__ Wbase,
             const float* __restrict__ bias, float* __restrict__ out32,
             __half* __restrict__ outh) {
    extern __shared__ char smraw[];
    __half* As = (__half*)smraw;                       // [128][XSH]
    __half* SW = (__half*)smraw + ABH;                 // 2 x [128][XSH]
    float* sbias = (float*)(smraw + OFF_BIAS);         // 128
    int*   srp   = (int*)(smraw + OFF_RP);             // 1025

    const int tid = threadIdx.x, wid = tid >> 5, lane = tid & 31;
    const int row0 = blockIdx.x * 128;
    const int seg0 = row0 * NR;
    const int sub = lane >> 3, sl = lane & 7;
    const uint4 Z4 = make_uint4(0u, 0u, 0u, 0u);

    for (int i = tid; i < 1025; i += 256) {
        int s = seg0 + i;
        srp[i] = (s <= SEG) ? g_rowptr[s] : EE;
    }
    if (tid < 128) sbias[tid] = bias[tid];

    // prefetch W[0] (group committed below together with nothing else)
    for (int c = tid; c < 2048; c += 256) {
        int k = c >> 4, c8 = c & 15;
        cp_async16(sptr(SW + k * XSH + c8 * 8), Wbase + k * DD + c8 * 8);
    }
    CP_COMMIT();
    __syncthreads();   // srp visible

    float acc[2][8][4];
#pragma unroll
    for (int mi = 0; mi < 2; mi++)
#pragma unroll
        for (int ni = 0; ni < 8; ni++)
#pragma unroll
            for (int j = 0; j < 4; j++) acc[mi][ni][j] = 0.f;

    const int m0 = (wid >> 1) * 32, n0 = (wid & 1) * 64;
    const int arow = lane & 15, acol8 = (lane >> 4) * 8;

    for (int w = 0; w < NW; w++) {
        // ---- stage A-tile for this block ----
        if (w < NR) {
#pragma unroll 1
            for (int g4 = 0; g4 < 4; g4++) {
                int row = wid * 16 + g4 * 4 + sub;
                int idx = row * NR + w;
                int e = srp[idx];
                const int e1 = srp[idx + 1];
                const int dg = e1 - e;
                __half* dst = As + row * XSH + sl * 16;
                if (dg == 0) {
                    *(uint4*)dst = Z4;
                    *(uint4*)(dst + 8) = Z4;
                } else if (dg == 1) {
                    // mean of one row == the row: direct global->smem copy
                    int s0 = g_esrc[e];
                    const __half* srcp = Xsrc + (size_t)s0 * DD + sl * 16;
                    cp_async16(sptr(dst), srcp);
                    cp_async16(sptr(dst) + 16, srcp + 8);
                } else {
                    float af[16];
#pragma unroll
                    for (int q = 0; q < 16; q++) af[q] = 0.f;
                    // 2-edge unroll: MLP 4
                    for (; e + 2 <= e1; e += 2) {
                        int s0 = g_esrc[e], s1 = g_esrc[e + 1];
                        const uint4* p0 = (const uint4*)(Xsrc + (size_t)s0 * DD) + sl * 2;
                        const uint4* p1 = (const uint4*)(Xsrc + (size_t)s1 * DD) + sl * 2;
                        uint4 a0 = p0[0], a1 = p0[1];
                        uint4 b0 = p1[0], b1 = p1[1];
                        addrow(af, a0, a1);
                        addrow(af, b0, b1);
                    }
                    if (e < e1) {
                        int s0 = g_esrc[e];
                        const uint4* p0 = (const uint4*)(Xsrc + (size_t)s0 * DD) + sl * 2;
                        addrow(af, p0[0], p0[1]);
                    }
                    float s = 1.0f / (float)dg;
                    uint4 o0, o1;
                    __half2* h0 = (__half2*)&o0;
                    __half2* h1 = (__half2*)&o1;
#pragma unroll
                    for (int q = 0; q < 4; q++) {
                        h0[q] = __floats2half2_rn(af[2 * q] * s, af[2 * q + 1] * s);
                        h1[q] = __floats2half2_rn(af[8 + 2 * q] * s, af[8 + 2 * q + 1] * s);
                    }
                    *(uint4*)dst = o0;
                    *(uint4*)(dst + 8) = o1;
                }
            }
        } else {
            // root block: contiguous rows via cp.async
            for (int c = tid; c < 2048; c += 256) {
                int r = c >> 4, c8 = c & 15;
                int g = row0 + r;
                if (g < NN)
                    cp_async16(sptr(As + r * XSH + c8 * 8), Xsrc + (size_t)g * DD + c8 * 8);
                else
                    *(uint4*)(As + r * XSH + c8 * 8) = Z4;
            }
        }
        CP_COMMIT();   // group: this block's A-tile cp.asyncs (may be empty)

        // ---- prefetch W[w+1], then wait for A-tile + W[w] ----
        if (w + 1 < NW) {
            const __half* srcW = Wbase + (size_t)(w + 1) * DD * DD;
            __half* wd = SW + ((w + 1) & 1) * ABH;
            for (int c = tid; c < 2048; c += 256) {
                int k = c >> 4, c8 = c & 15;
                cp_async16(sptr(wd + k * XSH + c8 * 8), srcW + k * DD + c8 * 8);
            }
            CP_COMMIT();
            CP_WAIT(1);      // all but W[w+1]: A-tile(w) + W(w) complete
        } else {
            CP_WAIT(0);
        }
        __syncthreads();

        // ---- MMA K-block ----
        __half* Wc = SW + (w & 1) * ABH;
#pragma unroll
        for (int k0 = 0; k0 < 128; k0 += 16) {
            uint32_t a[2][4];
#pragma unroll
            for (int mi = 0; mi < 2; mi++)
                ldsm4(a[mi], sptr(As + (m0 + mi * 16 + arow) * XSH + k0 + acol8));
            uint32_t bb[4][4];
#pragma unroll
            for (int np = 0; np < 4; np++)
                ldsm4t(bb[np], sptr(Wc + (k0 + arow) * XSH + n0 + np * 16 + acol8));
#pragma unroll
            for (int mi = 0; mi < 2; mi++)
#pragma unroll
                for (int ni = 0; ni < 8; ni++)
                    mma_f16(acc[mi][ni], a[mi],
                            bb[ni >> 1][(ni & 1) * 2], bb[ni >> 1][(ni & 1) * 2 + 1]);
        }
        __syncthreads();   // done reading As before next staging overwrites it
    }

    // ---- epilogue: single output write ----
#pragma unroll
    for (int mi = 0; mi < 2; mi++) {
#pragma unroll
        for (int part = 0; part < 2; part++) {
            int row = m0 + mi * 16 + (lane >> 2) + part * 8;
            int g = row0 + row;
            if (g < NN) {
                if (out32) {
                    float* base = out32 + (size_t)g * DD;
#pragma unroll
                    for (int ni = 0; ni < 8; ni++) {
                        int col = n0 + ni * 8 + 2 * (lane & 3);
                        float2 v;
                        v.x = acc[mi][ni][part * 2] + sbias[col];
                        v.y = acc[mi][ni][part * 2 + 1] + sbias[col + 1];
                        *(float2*)(base + col) = v;
                    }
                } else {
                    __half* base = outh + (size_t)g * DD;
#pragma unroll
                    for (int ni = 0; ni < 8; ni++) {
                        int col = n0 + ni * 8 + 2 * (lane & 3);
                        float vx = fmaxf(acc[mi][ni][part * 2] + sbias[col], 0.f);
                        float vy = fmaxf(acc[mi][ni][part * 2 + 1] + sbias[col + 1], 0.f);
                        *(__half2*)(base + col) = __floats2half2_rn(vx, vy);
                    }
                }
            }
        }
    }
}

// ---------------------------------------------------------------------------
extern "C" void kernel_launch(void* const* d_in, const int* in_sizes, int n_in,
                              void* d_out, int out_size) {
    const int*   ei     = (const int*)d_in[0];
    const int*   et     = (const int*)d_in[1];
    const float* emb    = (const float*)d_in[2];
    const float* basis1 = (const float*)d_in[3];
    const float* comp1  = (const float*)d_in[4];
    const float* root1  = (const float*)d_in[5];
    const float* bias1  = (const float*)d_in[6];
    const float* basis2 = (const float*)d_in[7];
    const float* comp2  = (const float*)d_in[8];
    const float* root2  = (const float*)d_in[9];
    const float* bias2  = (const float*)d_in[10];
    float* out = (float*)d_out;

    cudaFuncSetAttribute(fused_kernel, cudaFuncAttributeMaxDynamicSharedMemorySize,
                         SMEMB);

    __half *xh, *x1h, *wh;
    cudaGetSymbolAddress((void**)&xh, g_xh);
    cudaGetSymbolAddress((void**)&x1h, g_x1h);
    cudaGetSymbolAddress((void**)&wh, g_Wh);

    init_kernel<<<12500, 256>>>(emb);
    count_kernel<<<NBLK2, 256>>>(ei, et);
    scan1_kernel<<<NBLK2, 256>>>();
    scan2_kernel<<<1, 1024>>>();
    scan3_kernel<<<NBLK2, 256>>>();
    fill_kernel<<<NBLK2, 256>>>(ei, et);
    prep_wh_kernel<<<1152, 256>>>(comp1, basis1, root1, comp2, basis2, root2);

    // layer 1: g_xh -> relu -> g_x1h (fp16)
    fused_kernel<<<NTILES, 256, SMEMB>>>(xh, wh, bias1, nullptr, x1h);
    // layer 2: g_x1h -> out (fp32 + bias)
    fused_kernel<<<NTILES, 256, SMEMB>>>(x1h, wh + NW * DD * DD, bias2, out, nullptr);
}